// round 15
// baseline (speedup 1.0000x reference)
#include <cuda_runtime.h>
#include <cstdint>

// Problem constants
#define Bc   8
#define Tc   256
#define Uc   64
#define Dc   640
#define Vc   1024
#define K2c  1280
#define MOUT (Bc*Tc*Uc)     // 131072 output rows
#define NIT  (Dc/32)        // 20 k-iterations

// Device scratch
__device__ __align__(16) float g_encT[Bc*Tc*Dc];   // relu+tf32(enc)  5.24 MB
__device__ __align__(16) float g_Wtf [Vc*K2c];     // tf32(W)         5.24 MB
__device__ __align__(16) float g_P   [Bc*Uc*Vc];   // P = ReLU(pred)@Wp^T + b

__device__ __forceinline__ uint32_t f2tf(float x) {
    uint32_t r;
    asm("cvt.rna.tf32.f32 %0, %1;" : "=r"(r) : "f"(x));
    return r;
}
__device__ __forceinline__ void cpa(uint32_t dst, const float* src) {
    asm volatile("cp.async.ca.shared.global [%0], [%1], 16;\n"
                 :: "r"(dst), "l"(src));
}
#define CP_COMMIT() asm volatile("cp.async.commit_group;\n" ::: "memory")
#define CP_WAIT2()  asm volatile("cp.async.wait_group 2;\n" ::: "memory")
#define CP_WAIT0()  asm volatile("cp.async.wait_group 0;\n" ::: "memory")

// ---------------------------------------------------------------------------
// Prologue launch: blocks [0,64) compute the P GEMM (R5-style, raw inputs,
// in-register tf32); blocks [64, ...) transform enc (relu+tf32) and W (tf32).
// Block 64 also writes the passthrough length tail.
// ---------------------------------------------------------------------------
#define PB   64                       // pgemm blocks
#define NE4  (Bc*Tc*Dc/4)
#define NW4  (Vc*K2c/4)
#define NTR  ((NE4 + NW4 + 255)/256)  // transform blocks

__global__ __launch_bounds__(256) void prep_kernel(
    const float4* __restrict__ enc4,
    const float* __restrict__ pred,
    const float* __restrict__ W,
    const float4* __restrict__ W4,
    const float* __restrict__ bias,
    float* __restrict__ out,
    const int* __restrict__ slen,
    const int* __restrict__ tlen,
    int writeTail)
{
    __shared__ uint32_t As[64][36];
    __shared__ uint32_t Bs[128][36];

    const int tid = threadIdx.x;

    if (blockIdx.x >= PB) {
        // ---------------- transform branch: enc then W ----------------
        int idx = (blockIdx.x - PB) * 256 + tid;
        if (idx < NE4) {
            float4 v = enc4[idx];
            uint4 o;
            o.x = f2tf(fmaxf(v.x, 0.f)); o.y = f2tf(fmaxf(v.y, 0.f));
            o.z = f2tf(fmaxf(v.z, 0.f)); o.w = f2tf(fmaxf(v.w, 0.f));
            ((uint4*)g_encT)[idx] = o;
        } else if (idx < NE4 + NW4) {
            float4 v = W4[idx - NE4];
            uint4 o;
            o.x = f2tf(v.x); o.y = f2tf(v.y); o.z = f2tf(v.z); o.w = f2tf(v.w);
            ((uint4*)g_Wtf)[idx - NE4] = o;
        }
        if (writeTail && blockIdx.x == PB && tid < 16) {
            size_t tb = (size_t)MOUT * Vc;
            if (tid < 8) out[tb + tid] = (float)slen[tid];
            else         out[tb + tid] = (float)tlen[tid - 8];
        }
        return;
    }

    // ---------------- pgemm branch: 64x128 tile of P ----------------
    const int bn0 = (blockIdx.x & 7) * 128;    // v-cols
    const int bm0 = (blockIdx.x >> 3) * 64;    // rows in [0,512)
    const int warp = tid >> 5;
    const int lane = tid & 31;
    const int g    = lane >> 2;
    const int q    = lane & 3;
    const int lr   = tid >> 3;
    const int lc   = (tid & 7) * 4;
    const int mg   = warp & 3;                 // 4 m-groups x 16 rows
    const int ng   = warp >> 2;                // 2 n-groups x 64 cols

    float c[8][4];
#pragma unroll
    for (int nt = 0; nt < 8; nt++)
#pragma unroll
        for (int r = 0; r < 4; r++) c[nt][r] = 0.f;

    float4 ra[2], rw[4];
#pragma unroll
    for (int i = 0; i < 2; i++)
        ra[i] = *(const float4*)&pred[(size_t)(bm0 + lr + i * 32) * Dc + lc];
#pragma unroll
    for (int i = 0; i < 4; i++)
        rw[i] = *(const float4*)&W[(size_t)(bn0 + lr + i * 32) * K2c + Dc + lc];

    for (int k0 = 0; k0 < Dc; k0 += 32) {
#pragma unroll
        for (int i = 0; i < 2; i++) {
            int row = lr + i * 32;
            As[row][lc+0] = f2tf(fmaxf(ra[i].x, 0.f));
            As[row][lc+1] = f2tf(fmaxf(ra[i].y, 0.f));
            As[row][lc+2] = f2tf(fmaxf(ra[i].z, 0.f));
            As[row][lc+3] = f2tf(fmaxf(ra[i].w, 0.f));
        }
#pragma unroll
        for (int i = 0; i < 4; i++) {
            int row = lr + i * 32;
            Bs[row][lc+0] = f2tf(rw[i].x);
            Bs[row][lc+1] = f2tf(rw[i].y);
            Bs[row][lc+2] = f2tf(rw[i].z);
            Bs[row][lc+3] = f2tf(rw[i].w);
        }
        __syncthreads();
        if (k0 + 32 < Dc) {
#pragma unroll
            for (int i = 0; i < 2; i++)
                ra[i] = *(const float4*)&pred[(size_t)(bm0 + lr + i * 32) * Dc + k0 + 32 + lc];
#pragma unroll
            for (int i = 0; i < 4; i++)
                rw[i] = *(const float4*)&W[(size_t)(bn0 + lr + i * 32) * K2c + Dc + k0 + 32 + lc];
        }
#pragma unroll
        for (int kk = 0; kk < 4; kk++) {
            uint32_t af[4];
            af[0] = As[mg*16 + g    ][kk*8 + q    ];
            af[1] = As[mg*16 + g + 8][kk*8 + q    ];
            af[2] = As[mg*16 + g    ][kk*8 + q + 4];
            af[3] = As[mg*16 + g + 8][kk*8 + q + 4];
#pragma unroll
            for (int nt = 0; nt < 8; nt++) {
                int n = ng*64 + nt*8 + g;
                uint32_t b0 = Bs[n][kk*8 + q];
                uint32_t b1 = Bs[n][kk*8 + q + 4];
                asm volatile(
                    "mma.sync.aligned.m16n8k8.row.col.f32.tf32.tf32.f32 "
                    "{%0,%1,%2,%3}, {%4,%5,%6,%7}, {%8,%9}, {%0,%1,%2,%3};\n"
                    : "+f"(c[nt][0]), "+f"(c[nt][1]), "+f"(c[nt][2]), "+f"(c[nt][3])
                    : "r"(af[0]), "r"(af[1]), "r"(af[2]), "r"(af[3]),
                      "r"(b0), "r"(b1));
            }
        }
        __syncthreads();
    }

    {
        int row = bm0 + mg * 16 + g;
#pragma unroll
        for (int nt = 0; nt < 8; nt++) {
            int col = bn0 + ng*64 + nt*8 + q*2;
            float b0 = bias[col], b1 = bias[col + 1];
            g_P[(size_t)row * Vc + col]           = c[nt][0] + b0;
            g_P[(size_t)row * Vc + col + 1]       = c[nt][1] + b1;
            g_P[(size_t)(row + 8) * Vc + col]     = c[nt][2] + b0;
            g_P[(size_t)(row + 8) * Vc + col + 1] = c[nt][3] + b1;
        }
    }
}

// 192 KB dynamic shared memory, 1 block/SM
struct __align__(16) Smem {
    float    P[64][128];        // 32 KB  P tile (cp.async from g_P, hidden)
    float    E[32][128];        // 16 KB  store-phase slab
    uint32_t As[4][128][36];    // 72 KB  enc staging, 4-stage ring
    uint32_t Bs[4][128][36];    // 72 KB  W staging, 4-stage ring
};

// ---------------------------------------------------------------------------
// Main kernel: P tile cp.async (1 group, drains under E pipeline) +
// E gemm (R8 pipeline, 20 iters) + store phase. grid (8,16), 512 threads.
// ---------------------------------------------------------------------------
__global__ __launch_bounds__(512, 1) void fused_joiner(
    float4* __restrict__ out)
{
    extern __shared__ char smem_raw[];
    Smem& sm = *reinterpret_cast<Smem*>(smem_raw);

    const int tid  = threadIdx.x;
    const int warp = tid >> 5;
    const int lane = tid & 31;
    const int g    = lane >> 2;
    const int q    = lane & 3;
    const int bn0  = blockIdx.x * 128;
    const int b    = blockIdx.y >> 1;
    const int bt0  = b * Tc + (blockIdx.y & 1) * 128;

    const int lr = tid >> 3;        // 0..63
    const int lc = (tid & 7) * 4;   // 0,4..28

    const uint32_t pB  = (uint32_t)__cvta_generic_to_shared(sm.P);
    const uint32_t asB = (uint32_t)__cvta_generic_to_shared(sm.As);
    const uint32_t bsB = (uint32_t)__cvta_generic_to_shared(sm.Bs);
    auto soff = [](int st, int row, int col) -> uint32_t {
        return (uint32_t)((((st * 128 + row) * 36) + col) * 4);
    };

    // ---- issue P-tile load as the FIRST cp.async group (2048 float4) ----
    {
        const float4* P4 = (const float4*)g_P;
#pragma unroll
        for (int j = 0; j < 4; j++) {
            int idx = tid + j * 512;
            int r = idx >> 5, cq = idx & 31;
            cpa(pB + (uint32_t)((r * 128 + cq * 4) * 4),
                (const float*)(P4 + (size_t)(b * Uc + r) * 256 + blockIdx.x * 32 + cq));
        }
        CP_COMMIT();
    }

    // ===================== Phase E: 128 x 128 (R8 pipeline) ================
    const int mgE = warp & 3;     // m-tiles {mgE, mgE+4}
    const int ngE = warp >> 2;
    float cE[2][4][4];
#pragma unroll
    for (int mt = 0; mt < 2; mt++)
#pragma unroll
        for (int nt = 0; nt < 4; nt++)
#pragma unroll
            for (int r = 0; r < 4; r++) cE[mt][nt][r] = 0.f;

    {
        auto issueE = [&](int st, int k0) {
            cpa(asB + soff(st, lr, lc),
                &g_encT[(size_t)(bt0 + lr) * Dc + k0 + lc]);
            cpa(asB + soff(st, lr + 64, lc),
                &g_encT[(size_t)(bt0 + lr + 64) * Dc + k0 + lc]);
            cpa(bsB + soff(st, lr, lc),
                &g_Wtf[(size_t)(bn0 + lr) * K2c + k0 + lc]);
            cpa(bsB + soff(st, lr + 64, lc),
                &g_Wtf[(size_t)(bn0 + lr + 64) * K2c + k0 + lc]);
        };

        issueE(0, 0);  CP_COMMIT();
        issueE(1, 32); CP_COMMIT();

#pragma unroll 1
        for (int it = 0; it < NIT; it++) {
            const int st = it & 3;
            const int nx = it + 2;
            if (nx < NIT) issueE(nx & 3, nx * 32);
            CP_COMMIT();
            CP_WAIT2();            // also retires the P group early (oldest)
            __syncthreads();
#pragma unroll
            for (int kk = 0; kk < 4; kk++) {
                uint32_t af[2][4];
#pragma unroll
                for (int mt = 0; mt < 2; mt++) {
                    int r0 = (mgE + 4*mt) * 16;
                    af[mt][0] = sm.As[st][r0 + g    ][kk*8 + q    ];
                    af[mt][1] = sm.As[st][r0 + g + 8][kk*8 + q    ];
                    af[mt][2] = sm.As[st][r0 + g    ][kk*8 + q + 4];
                    af[mt][3] = sm.As[st][r0 + g + 8][kk*8 + q + 4];
                }
#pragma unroll
                for (int nt = 0; nt < 4; nt++) {
                    int n = ngE*32 + nt*8 + g;
                    uint32_t b0 = sm.Bs[st][n][kk*8 + q];
                    uint32_t b1 = sm.Bs[st][n][kk*8 + q + 4];
#pragma unroll
                    for (int mt = 0; mt < 2; mt++) {
                        asm volatile(
                            "mma.sync.aligned.m16n8k8.row.col.f32.tf32.tf32.f32 "
                            "{%0,%1,%2,%3}, {%4,%5,%6,%7}, {%8,%9}, {%0,%1,%2,%3};\n"
                            : "+f"(cE[mt][nt][0]), "+f"(cE[mt][nt][1]),
                              "+f"(cE[mt][nt][2]), "+f"(cE[mt][nt][3])
                            : "r"(af[mt][0]), "r"(af[mt][1]), "r"(af[mt][2]), "r"(af[mt][3]),
                              "r"(b0), "r"(b1));
                    }
                }
            }
            __syncthreads();
        }
        CP_WAIT0();
        __syncthreads();
    }

    // ===================== Phase C: expand (4 slabs of 32 t) ===============
    const int vq = lane;
#pragma unroll 1
    for (int s = 0; s < 4; s++) {
#pragma unroll
        for (int mt = 0; mt < 2; mt++) {
            int mtile = mgE + 4 * mt;
            if ((mtile >> 1) == s) {
                int r0 = (mtile & 1) * 16 + g;
#pragma unroll
                for (int nt = 0; nt < 4; nt++) {
                    int col = ngE*32 + nt*8 + q*2;
                    sm.E[r0    ][col    ] = cE[mt][nt][0];
                    sm.E[r0    ][col + 1] = cE[mt][nt][1];
                    sm.E[r0 + 8][col    ] = cE[mt][nt][2];
                    sm.E[r0 + 8][col + 1] = cE[mt][nt][3];
                }
            }
        }
        __syncthreads();

        // warp w stores rows {2w, 2w+1}; per u: 1 LDS + 2 STG.cs
        float4 e0 = ((const float4*)sm.E[warp * 2    ])[vq];
        float4 e1 = ((const float4*)sm.E[warp * 2 + 1])[vq];
        size_t ob0 = (size_t)(bt0 + s * 32 + warp * 2) * (Uc * 256)
                     + blockIdx.x * 32 + vq;
        size_t ob1 = ob0 + (size_t)(Uc * 256);
#pragma unroll 4
        for (int u = 0; u < Uc; u++) {
            float4 p = ((const float4*)sm.P[u])[vq];
            float4 r0, r1;
            r0.x = e0.x + p.x; r0.y = e0.y + p.y; r0.z = e0.z + p.z; r0.w = e0.w + p.w;
            r1.x = e1.x + p.x; r1.y = e1.y + p.y; r1.z = e1.z + p.z; r1.w = e1.w + p.w;
            __stcs(&out[ob0 + (size_t)u * 256], r0);
            __stcs(&out[ob1 + (size_t)u * 256], r1);
        }
        __syncthreads();
    }
}

extern "C" void kernel_launch(void* const* d_in, const int* in_sizes, int n_in,
                              void* d_out, int out_size)
{
    const float* enc  = (const float*)d_in[0];  // [B,T,D]
    const int*   slen = (const int*)  d_in[1];  // [B]
    const float* pred = (const float*)d_in[2];  // [B,U,D]
    const int*   tlen = (const int*)  d_in[3];  // [B]
    const float* W    = (const float*)d_in[4];  // [V, 2D]
    const float* bias = (const float*)d_in[5];  // [V]
    float* out = (float*)d_out;

    int writeTail = (out_size >= (int)((size_t)MOUT * Vc + 16)) ? 1 : 0;

    // Prologue: 64 pgemm blocks (scheduled first) + enc/W transform blocks
    prep_kernel<<<PB + NTR, 256>>>(
        (const float4*)enc, pred, W, (const float4*)W, bias,
        out, slen, tlen, writeTail);

    int smemBytes = (int)sizeof(Smem);
    cudaFuncSetAttribute(fused_joiner,
                         cudaFuncAttributeMaxDynamicSharedMemorySize, smemBytes);
    fused_joiner<<<dim3(Vc / 128, 2 * Bc), 512, smemBytes>>>((float4*)out);
}

// round 16
// speedup vs baseline: 1.0605x; 1.0605x over previous
#include <cuda_runtime.h>
#include <cstdint>

// Problem constants
#define Bc   8
#define Tc   256
#define Uc   64
#define Dc   640
#define Vc   1024
#define K2c  1280
#define MOUT (Bc*Tc*Uc)     // 131072 output rows
#define NIT  (Dc/32)        // 20 k-iterations

// Device scratch
__device__ __align__(16) float g_encT[Bc*Tc*Dc];   // relu+tf32(enc)  5.24 MB
__device__ __align__(16) float g_Wtf [Vc*K2c];     // tf32(W)         5.24 MB
__device__ __align__(16) float g_P   [Bc*Uc*Vc];   // P = ReLU(pred)@Wp^T + b

__device__ __forceinline__ uint32_t f2tf(float x) {
    uint32_t r;
    asm("cvt.rna.tf32.f32 %0, %1;" : "=r"(r) : "f"(x));
    return r;
}
__device__ __forceinline__ uint32_t f2tfr(float x) { return f2tf(fmaxf(x, 0.f)); }
__device__ __forceinline__ void cpa(uint32_t dst, const float* src) {
    asm volatile("cp.async.ca.shared.global [%0], [%1], 16;\n"
                 :: "r"(dst), "l"(src));
}
#define CP_COMMIT() asm volatile("cp.async.commit_group;\n" ::: "memory")
#define CP_WAIT2()  asm volatile("cp.async.wait_group 2;\n" ::: "memory")
#define CP_WAIT0()  asm volatile("cp.async.wait_group 0;\n" ::: "memory")

// ---------------------------------------------------------------------------
// Prologue launch: blocks [0,64) compute the P GEMM with a 4-stage cp.async
// pipeline (raw pred/W staged; relu+tf32 at fragment load — identical values
// to R15). Blocks [64,...) transform enc (relu+tf32) and W (tf32).
// ---------------------------------------------------------------------------
#define PB   64
#define NE4  (Bc*Tc*Dc/4)
#define NW4  (Vc*K2c/4)
#define NTR  ((NE4 + NW4 + 255)/256)

// prep dynamic smem: raw fp32 staging, 4-stage ring (pgemm branch only)
struct __align__(16) PrepSmem {
    float As[4][64][36];     // 36 KB  pred staging
    float Bs[4][128][36];    // 72 KB  Wp staging
};

__global__ __launch_bounds__(256) void prep_kernel(
    const float4* __restrict__ enc4,
    const float* __restrict__ pred,
    const float* __restrict__ W,
    const float4* __restrict__ W4,
    const float* __restrict__ bias,
    float* __restrict__ out,
    const int* __restrict__ slen,
    const int* __restrict__ tlen,
    int writeTail)
{
    const int tid = threadIdx.x;

    if (blockIdx.x >= PB) {
        // ---------------- transform branch: enc then W ----------------
        int idx = (blockIdx.x - PB) * 256 + tid;
        if (idx < NE4) {
            float4 v = enc4[idx];
            uint4 o;
            o.x = f2tf(fmaxf(v.x, 0.f)); o.y = f2tf(fmaxf(v.y, 0.f));
            o.z = f2tf(fmaxf(v.z, 0.f)); o.w = f2tf(fmaxf(v.w, 0.f));
            ((uint4*)g_encT)[idx] = o;
        } else if (idx < NE4 + NW4) {
            float4 v = W4[idx - NE4];
            uint4 o;
            o.x = f2tf(v.x); o.y = f2tf(v.y); o.z = f2tf(v.z); o.w = f2tf(v.w);
            ((uint4*)g_Wtf)[idx - NE4] = o;
        }
        if (writeTail && blockIdx.x == PB && tid < 16) {
            size_t tb = (size_t)MOUT * Vc;
            if (tid < 8) out[tb + tid] = (float)slen[tid];
            else         out[tb + tid] = (float)tlen[tid - 8];
        }
        return;
    }

    // ---------------- pgemm branch: 64x128 tile of P, pipelined -----------
    extern __shared__ char psm_raw[];
    PrepSmem& psm = *reinterpret_cast<PrepSmem*>(psm_raw);

    const int bn0 = (blockIdx.x & 7) * 128;    // v-cols
    const int bm0 = (blockIdx.x >> 3) * 64;    // rows in [0,512)
    const int warp = tid >> 5;
    const int lane = tid & 31;
    const int g    = lane >> 2;
    const int q    = lane & 3;
    const int lr   = tid >> 3;                 // 0..31
    const int lc   = (tid & 7) * 4;
    const int mg   = warp & 3;                 // 4 m-groups x 16 rows
    const int ng   = warp >> 2;                // 2 n-groups x 64 cols

    const uint32_t asB = (uint32_t)__cvta_generic_to_shared(psm.As);
    const uint32_t bsB = (uint32_t)__cvta_generic_to_shared(psm.Bs);
    auto aoff = [](int st, int row, int col) -> uint32_t {
        return (uint32_t)((((st * 64 + row) * 36) + col) * 4);
    };
    auto boff = [](int st, int row, int col) -> uint32_t {
        return (uint32_t)((((st * 128 + row) * 36) + col) * 4);
    };

    auto issuePg = [&](int st, int k0) {
#pragma unroll
        for (int i = 0; i < 2; i++)
            cpa(asB + aoff(st, lr + i * 32, lc),
                &pred[(size_t)(bm0 + lr + i * 32) * Dc + k0 + lc]);
#pragma unroll
        for (int i = 0; i < 4; i++)
            cpa(bsB + boff(st, lr + i * 32, lc),
                &W[(size_t)(bn0 + lr + i * 32) * K2c + Dc + k0 + lc]);
    };

    float c[8][4];
#pragma unroll
    for (int nt = 0; nt < 8; nt++)
#pragma unroll
        for (int r = 0; r < 4; r++) c[nt][r] = 0.f;

    issuePg(0, 0);  CP_COMMIT();
    issuePg(1, 32); CP_COMMIT();

#pragma unroll 1
    for (int it = 0; it < NIT; it++) {
        const int st = it & 3;
        const int nx = it + 2;
        if (nx < NIT) issuePg(nx & 3, nx * 32);
        CP_COMMIT();
        CP_WAIT2();
        __syncthreads();
#pragma unroll
        for (int kk = 0; kk < 4; kk++) {
            uint32_t af[4];
            af[0] = f2tfr(psm.As[st][mg*16 + g    ][kk*8 + q    ]);
            af[1] = f2tfr(psm.As[st][mg*16 + g + 8][kk*8 + q    ]);
            af[2] = f2tfr(psm.As[st][mg*16 + g    ][kk*8 + q + 4]);
            af[3] = f2tfr(psm.As[st][mg*16 + g + 8][kk*8 + q + 4]);
#pragma unroll
            for (int nt = 0; nt < 8; nt++) {
                int n = ng*64 + nt*8 + g;
                uint32_t b0 = f2tf(psm.Bs[st][n][kk*8 + q]);
                uint32_t b1 = f2tf(psm.Bs[st][n][kk*8 + q + 4]);
                asm volatile(
                    "mma.sync.aligned.m16n8k8.row.col.f32.tf32.tf32.f32 "
                    "{%0,%1,%2,%3}, {%4,%5,%6,%7}, {%8,%9}, {%0,%1,%2,%3};\n"
                    : "+f"(c[nt][0]), "+f"(c[nt][1]), "+f"(c[nt][2]), "+f"(c[nt][3])
                    : "r"(af[0]), "r"(af[1]), "r"(af[2]), "r"(af[3]),
                      "r"(b0), "r"(b1));
            }
        }
        __syncthreads();
    }
    CP_WAIT0();

    {
        int row = bm0 + mg * 16 + g;
#pragma unroll
        for (int nt = 0; nt < 8; nt++) {
            int col = bn0 + ng*64 + nt*8 + q*2;
            float b0 = bias[col], b1 = bias[col + 1];
            g_P[(size_t)row * Vc + col]           = c[nt][0] + b0;
            g_P[(size_t)row * Vc + col + 1]       = c[nt][1] + b1;
            g_P[(size_t)(row + 8) * Vc + col]     = c[nt][2] + b0;
            g_P[(size_t)(row + 8) * Vc + col + 1] = c[nt][3] + b1;
        }
    }
}

// 192 KB dynamic shared memory, 1 block/SM (UNCHANGED from R15)
struct __align__(16) Smem {
    float    P[64][128];        // 32 KB  P tile (cp.async from g_P, hidden)
    float    E[32][128];        // 16 KB  store-phase slab
    uint32_t As[4][128][36];    // 72 KB  enc staging, 4-stage ring
    uint32_t Bs[4][128][36];    // 72 KB  W staging, 4-stage ring
};

// ---------------------------------------------------------------------------
// Main kernel (UNCHANGED from R15, measured 100.1 us): P tile cp.async +
// E gemm pipeline + store phase. grid (8,16), 512 threads.
// ---------------------------------------------------------------------------
__global__ __launch_bounds__(512, 1) void fused_joiner(
    float4* __restrict__ out)
{
    extern __shared__ char smem_raw[];
    Smem& sm = *reinterpret_cast<Smem*>(smem_raw);

    const int tid  = threadIdx.x;
    const int warp = tid >> 5;
    const int lane = tid & 31;
    const int g    = lane >> 2;
    const int q    = lane & 3;
    const int bn0  = blockIdx.x * 128;
    const int b    = blockIdx.y >> 1;
    const int bt0  = b * Tc + (blockIdx.y & 1) * 128;

    const int lr = tid >> 3;        // 0..63
    const int lc = (tid & 7) * 4;   // 0,4..28

    const uint32_t pB  = (uint32_t)__cvta_generic_to_shared(sm.P);
    const uint32_t asB = (uint32_t)__cvta_generic_to_shared(sm.As);
    const uint32_t bsB = (uint32_t)__cvta_generic_to_shared(sm.Bs);
    auto soff = [](int st, int row, int col) -> uint32_t {
        return (uint32_t)((((st * 128 + row) * 36) + col) * 4);
    };

    // ---- issue P-tile load as the FIRST cp.async group (2048 float4) ----
    {
        const float4* P4 = (const float4*)g_P;
#pragma unroll
        for (int j = 0; j < 4; j++) {
            int idx = tid + j * 512;
            int r = idx >> 5, cq = idx & 31;
            cpa(pB + (uint32_t)((r * 128 + cq * 4) * 4),
                (const float*)(P4 + (size_t)(b * Uc + r) * 256 + blockIdx.x * 32 + cq));
        }
        CP_COMMIT();
    }

    // ===================== Phase E: 128 x 128 =====================
    const int mgE = warp & 3;     // m-tiles {mgE, mgE+4}
    const int ngE = warp >> 2;
    float cE[2][4][4];
#pragma unroll
    for (int mt = 0; mt < 2; mt++)
#pragma unroll
        for (int nt = 0; nt < 4; nt++)
#pragma unroll
            for (int r = 0; r < 4; r++) cE[mt][nt][r] = 0.f;

    {
        auto issueE = [&](int st, int k0) {
            cpa(asB + soff(st, lr, lc),
                &g_encT[(size_t)(bt0 + lr) * Dc + k0 + lc]);
            cpa(asB + soff(st, lr + 64, lc),
                &g_encT[(size_t)(bt0 + lr + 64) * Dc + k0 + lc]);
            cpa(bsB + soff(st, lr, lc),
                &g_Wtf[(size_t)(bn0 + lr) * K2c + k0 + lc]);
            cpa(bsB + soff(st, lr + 64, lc),
                &g_Wtf[(size_t)(bn0 + lr + 64) * K2c + k0 + lc]);
        };

        issueE(0, 0);  CP_COMMIT();
        issueE(1, 32); CP_COMMIT();

#pragma unroll 1
        for (int it = 0; it < NIT; it++) {
            const int st = it & 3;
            const int nx = it + 2;
            if (nx < NIT) issueE(nx & 3, nx * 32);
            CP_COMMIT();
            CP_WAIT2();            // also retires the P group early (oldest)
            __syncthreads();
#pragma unroll
            for (int kk = 0; kk < 4; kk++) {
                uint32_t af[2][4];
#pragma unroll
                for (int mt = 0; mt < 2; mt++) {
                    int r0 = (mgE + 4*mt) * 16;
                    af[mt][0] = sm.As[st][r0 + g    ][kk*8 + q    ];
                    af[mt][1] = sm.As[st][r0 + g + 8][kk*8 + q    ];
                    af[mt][2] = sm.As[st][r0 + g    ][kk*8 + q + 4];
                    af[mt][3] = sm.As[st][r0 + g + 8][kk*8 + q + 4];
                }
#pragma unroll
                for (int nt = 0; nt < 4; nt++) {
                    int n = ngE*32 + nt*8 + g;
                    uint32_t b0 = sm.Bs[st][n][kk*8 + q];
                    uint32_t b1 = sm.Bs[st][n][kk*8 + q + 4];
#pragma unroll
                    for (int mt = 0; mt < 2; mt++) {
                        asm volatile(
                            "mma.sync.aligned.m16n8k8.row.col.f32.tf32.tf32.f32 "
                            "{%0,%1,%2,%3}, {%4,%5,%6,%7}, {%8,%9}, {%0,%1,%2,%3};\n"
                            : "+f"(cE[mt][nt][0]), "+f"(cE[mt][nt][1]),
                              "+f"(cE[mt][nt][2]), "+f"(cE[mt][nt][3])
                            : "r"(af[mt][0]), "r"(af[mt][1]), "r"(af[mt][2]), "r"(af[mt][3]),
                              "r"(b0), "r"(b1));
                    }
                }
            }
            __syncthreads();
        }
        CP_WAIT0();
        __syncthreads();
    }

    // ===================== Phase C: expand (4 slabs of 32 t) ===============
    const int vq = lane;
#pragma unroll 1
    for (int s = 0; s < 4; s++) {
#pragma unroll
        for (int mt = 0; mt < 2; mt++) {
            int mtile = mgE + 4 * mt;
            if ((mtile >> 1) == s) {
                int r0 = (mtile & 1) * 16 + g;
#pragma unroll
                for (int nt = 0; nt < 4; nt++) {
                    int col = ngE*32 + nt*8 + q*2;
                    sm.E[r0    ][col    ] = cE[mt][nt][0];
                    sm.E[r0    ][col + 1] = cE[mt][nt][1];
                    sm.E[r0 + 8][col    ] = cE[mt][nt][2];
                    sm.E[r0 + 8][col + 1] = cE[mt][nt][3];
                }
            }
        }
        __syncthreads();

        // warp w stores rows {2w, 2w+1}; per u: 1 LDS + 2 STG.cs
        float4 e0 = ((const float4*)sm.E[warp * 2    ])[vq];
        float4 e1 = ((const float4*)sm.E[warp * 2 + 1])[vq];
        size_t ob0 = (size_t)(bt0 + s * 32 + warp * 2) * (Uc * 256)
                     + blockIdx.x * 32 + vq;
        size_t ob1 = ob0 + (size_t)(Uc * 256);
#pragma unroll 4
        for (int u = 0; u < Uc; u++) {
            float4 p = ((const float4*)sm.P[u])[vq];
            float4 r0, r1;
            r0.x = e0.x + p.x; r0.y = e0.y + p.y; r0.z = e0.z + p.z; r0.w = e0.w + p.w;
            r1.x = e1.x + p.x; r1.y = e1.y + p.y; r1.z = e1.z + p.z; r1.w = e1.w + p.w;
            __stcs(&out[ob0 + (size_t)u * 256], r0);
            __stcs(&out[ob1 + (size_t)u * 256], r1);
        }
        __syncthreads();
    }
}

extern "C" void kernel_launch(void* const* d_in, const int* in_sizes, int n_in,
                              void* d_out, int out_size)
{
    const float* enc  = (const float*)d_in[0];  // [B,T,D]
    const int*   slen = (const int*)  d_in[1];  // [B]
    const float* pred = (const float*)d_in[2];  // [B,U,D]
    const int*   tlen = (const int*)  d_in[3];  // [B]
    const float* W    = (const float*)d_in[4];  // [V, 2D]
    const float* bias = (const float*)d_in[5];  // [V]
    float* out = (float*)d_out;

    int writeTail = (out_size >= (int)((size_t)MOUT * Vc + 16)) ? 1 : 0;

    int prepSmem = (int)sizeof(PrepSmem);
    cudaFuncSetAttribute(prep_kernel,
                         cudaFuncAttributeMaxDynamicSharedMemorySize, prepSmem);
    prep_kernel<<<PB + NTR, 256, prepSmem>>>(
        (const float4*)enc, pred, W, (const float4*)W, bias,
        out, slen, tlen, writeTail);

    int smemBytes = (int)sizeof(Smem);
    cudaFuncSetAttribute(fused_joiner,
                         cudaFuncAttributeMaxDynamicSharedMemorySize, smemBytes);
    fused_joiner<<<dim3(Vc / 128, 2 * Bc), 512, smemBytes>>>((float4*)out);
}